// round 1
// baseline (speedup 1.0000x reference)
#include <cuda_runtime.h>

// Problem constants
#define BB   8
#define TT   2048
#define NXC  1024
#define NHC  1024
#define MTOT (BB * TT)   // 16384

// Scratch (device globals — no allocation allowed in kernel_launch)
__device__ float g_q[(size_t)MTOT * NHC];          // 64 MB
__device__ float g_k[(size_t)MTOT * NHC];          // 64 MB
__device__ float g_v[(size_t)MTOT * NHC];          // 64 MB
__device__ float g_s[(size_t)BB * TT * TT];        // 134 MB (scores / attn)
__device__ float g_o[(size_t)MTOT * NHC];          // 64 MB (attn @ v)

// ---------------------------------------------------------------------------
// Classic 128x128x8 SGEMM, 256 threads, 8x8 strided micro-tile per thread.
//   NT = true : C[M,N] = A[M,K] @ B[N,K]^T   (both row-major, dot of rows)
//   NT = false: C[M,N] = A[M,K] @ B[K,N]     (row-major NN)
// grid = (N/128, M/128, batch); batch strides sA/sB/sC in elements.
// All dims here are multiples of 128 (M,N) and 8 (K) — no bounds checks.
// ---------------------------------------------------------------------------
template <bool NT>
__global__ __launch_bounds__(256) void gemm128(
    const float* __restrict__ A, const float* __restrict__ B,
    float* __restrict__ C,
    int N, int K, long long sA, long long sB, long long sC, float alpha)
{
    __shared__ __align__(16) float As[8][128];
    __shared__ __align__(16) float Bs[8][128];

    const int tid = threadIdx.x;
    const long long bz = blockIdx.z;
    A += bz * sA;  B += bz * sB;  C += bz * sC;

    const int row0 = blockIdx.y * 128;
    const int col0 = blockIdx.x * 128;

    // A-tile loading: 128 rows x 8 k, one float4 per thread
    const int lrow = tid >> 1;          // 0..127
    const int lk   = (tid & 1) * 4;     // 0 or 4
    const float* Ap = A + (long long)(row0 + lrow) * K + lk;

    // B-tile loading
    const float* Bp;
    int bk_row = 0, bcol4 = 0;
    if (NT) {
        Bp = B + (long long)(col0 + lrow) * K + lk;
    } else {
        bk_row = tid >> 5;              // 0..7
        bcol4  = (tid & 31) * 4;        // 0..124
        Bp = B + (long long)bk_row * N + col0 + bcol4;
    }

    // Compute mapping: strided 8x8 tile -> conflict-free LDS.128
    const int tr = tid >> 4;            // 0..15
    const int tc = tid & 15;            // 0..15

    float acc[8][8] = {};

    for (int kt = 0; kt < K; kt += 8) {
        float4 a4 = *(const float4*)(Ap);  Ap += 8;
        As[lk + 0][lrow] = a4.x;  As[lk + 1][lrow] = a4.y;
        As[lk + 2][lrow] = a4.z;  As[lk + 3][lrow] = a4.w;

        if (NT) {
            float4 b4 = *(const float4*)(Bp);  Bp += 8;
            Bs[lk + 0][lrow] = b4.x;  Bs[lk + 1][lrow] = b4.y;
            Bs[lk + 2][lrow] = b4.z;  Bs[lk + 3][lrow] = b4.w;
        } else {
            float4 b4 = *(const float4*)(Bp);  Bp += (long long)8 * N;
            *(float4*)&Bs[bk_row][bcol4] = b4;
        }
        __syncthreads();

#pragma unroll
        for (int k = 0; k < 8; ++k) {
            float4 a0 = *(const float4*)&As[k][tr * 4];
            float4 a1 = *(const float4*)&As[k][64 + tr * 4];
            float4 b0 = *(const float4*)&Bs[k][tc * 4];
            float4 b1 = *(const float4*)&Bs[k][64 + tc * 4];
            float ar[8] = {a0.x, a0.y, a0.z, a0.w, a1.x, a1.y, a1.z, a1.w};
            float br[8] = {b0.x, b0.y, b0.z, b0.w, b1.x, b1.y, b1.z, b1.w};
#pragma unroll
            for (int i = 0; i < 8; ++i)
#pragma unroll
                for (int j = 0; j < 8; ++j)
                    acc[i][j] += ar[i] * br[j];
        }
        __syncthreads();
    }

    // Epilogue: rows {tr*4+i, 64+tr*4+i}, cols {tc*4+j, 64+tc*4+j}
#pragma unroll
    for (int ig = 0; ig < 2; ++ig)
#pragma unroll
        for (int i = 0; i < 4; ++i) {
            int r = row0 + ig * 64 + tr * 4 + i;
#pragma unroll
            for (int jg = 0; jg < 2; ++jg) {
                float4 o;
                o.x = alpha * acc[ig * 4 + i][jg * 4 + 0];
                o.y = alpha * acc[ig * 4 + i][jg * 4 + 1];
                o.z = alpha * acc[ig * 4 + i][jg * 4 + 2];
                o.w = alpha * acc[ig * 4 + i][jg * 4 + 3];
                *(float4*)&C[(long long)r * N + col0 + jg * 64 + tc * 4] = o;
            }
        }
}

// ---------------------------------------------------------------------------
// Row softmax over TT=2048 columns. One block (256 threads) per row.
// ---------------------------------------------------------------------------
__global__ __launch_bounds__(256) void softmax_rows(float* __restrict__ S)
{
    __shared__ float red[8];
    float* p = S + (long long)blockIdx.x * TT;
    const int tid = threadIdx.x;

    float vals[8];
    float m = -3.4e38f;
#pragma unroll
    for (int i = 0; i < 8; ++i) {
        vals[i] = p[tid + 256 * i];
        m = fmaxf(m, vals[i]);
    }
#pragma unroll
    for (int o = 16; o > 0; o >>= 1)
        m = fmaxf(m, __shfl_xor_sync(0xffffffffu, m, o));
    if ((tid & 31) == 0) red[tid >> 5] = m;
    __syncthreads();
    float M = red[0];
#pragma unroll
    for (int i = 1; i < 8; ++i) M = fmaxf(M, red[i]);

    float s = 0.0f;
#pragma unroll
    for (int i = 0; i < 8; ++i) {
        vals[i] = __expf(vals[i] - M);
        s += vals[i];
    }
#pragma unroll
    for (int o = 16; o > 0; o >>= 1)
        s += __shfl_xor_sync(0xffffffffu, s, o);
    __syncthreads();                     // done reading red (max phase)
    if ((tid & 31) == 0) red[tid >> 5] = s;
    __syncthreads();
    float tot = red[0];
#pragma unroll
    for (int i = 1; i < 8; ++i) tot += red[i];

    float inv = 1.0f / tot;
#pragma unroll
    for (int i = 0; i < 8; ++i) p[tid + 256 * i] = vals[i] * inv;
}

// ---------------------------------------------------------------------------
// Launch sequence (graph-capturable: kernel launches only)
// ---------------------------------------------------------------------------
extern "C" void kernel_launch(void* const* d_in, const int* in_sizes, int n_in,
                              void* d_out, int out_size)
{
    (void)in_sizes; (void)n_in; (void)out_size;
    const float* x  = (const float*)d_in[0];
    const float* Wq = (const float*)d_in[1];
    const float* Wk = (const float*)d_in[2];
    const float* Wv = (const float*)d_in[3];
    const float* Wo = (const float*)d_in[4];
    float* out = (float*)d_out;

    float *q, *k, *v, *s, *o;
    cudaGetSymbolAddress((void**)&q, g_q);
    cudaGetSymbolAddress((void**)&k, g_k);
    cudaGetSymbolAddress((void**)&v, g_v);
    cudaGetSymbolAddress((void**)&s, g_s);
    cudaGetSymbolAddress((void**)&o, g_o);

    const dim3 blk(256);

    // 1) QKV projections: [16384,1024] = x @ W^T
    {
        dim3 g(NHC / 128, MTOT / 128, 1);   // (8, 128)
        gemm128<true><<<g, blk>>>(x, Wq, q, NHC, NXC, 0, 0, 0, 1.0f);
        gemm128<true><<<g, blk>>>(x, Wk, k, NHC, NXC, 0, 0, 0, 1.0f);
        gemm128<true><<<g, blk>>>(x, Wv, v, NHC, NXC, 0, 0, 0, 1.0f);
    }

    // 2) Scores: per batch S = q @ k^T / sqrt(T)
    {
        dim3 g(TT / 128, TT / 128, BB);     // (16, 16, 8)
        const float alpha = 0.022097086912079608f;   // 1/sqrt(2048)
        gemm128<true><<<g, blk>>>(q, k, s, TT, NHC,
                                  (long long)TT * NHC, (long long)TT * NHC,
                                  (long long)TT * TT, alpha);
    }

    // 3) Row softmax over all 16384 rows
    softmax_rows<<<BB * TT, blk>>>(s);

    // 4) attn @ v (NN GEMM per batch)
    {
        dim3 g(NHC / 128, TT / 128, BB);    // (8, 16, 8)
        gemm128<false><<<g, blk>>>(s, v, o, NHC, TT,
                                   (long long)TT * TT, (long long)TT * NHC,
                                   (long long)TT * NHC, 1.0f);
    }

    // 5) Output projection: out = o @ Wo^T
    {
        dim3 g(NHC / 128, MTOT / 128, 1);   // (8, 128)
        gemm128<true><<<g, blk>>>(o, Wo, out, NHC, NHC, 0, 0, 0, 1.0f);
    }
}

// round 3
// speedup vs baseline: 2.6876x; 2.6876x over previous
#include <cuda_runtime.h>
#include <cuda_bf16.h>
#include <cstdint>

#define BB   8
#define TT   2048
#define NXC  1024
#define NHC  1024
#define MTOT (BB * TT)   // 16384

// ---------------------------------------------------------------------------
// Scratch (device globals — no allocation allowed anywhere)
// ---------------------------------------------------------------------------
__device__ __nv_bfloat16 g_xhi[(size_t)MTOT * NXC], g_xlo[(size_t)MTOT * NXC];
__device__ __nv_bfloat16 g_wqhi[NHC * NXC], g_wqlo[NHC * NXC];
__device__ __nv_bfloat16 g_wkhi[NHC * NXC], g_wklo[NHC * NXC];
__device__ __nv_bfloat16 g_wvhi[NHC * NXC], g_wvlo[NHC * NXC];
__device__ __nv_bfloat16 g_wohi[NHC * NHC], g_wolo[NHC * NHC];
__device__ __nv_bfloat16 g_qhi[(size_t)MTOT * NHC], g_qlo[(size_t)MTOT * NHC];
__device__ __nv_bfloat16 g_khi[(size_t)MTOT * NHC], g_klo[(size_t)MTOT * NHC];
__device__ __nv_bfloat16 g_vthi[(size_t)NHC * MTOT], g_vtlo[(size_t)NHC * MTOT];
__device__ float         g_s[(size_t)BB * TT * TT];
__device__ __nv_bfloat16 g_phi[(size_t)BB * TT * TT], g_plo[(size_t)BB * TT * TT];
__device__ __nv_bfloat16 g_ohi[(size_t)MTOT * NHC], g_olo[(size_t)MTOT * NHC];

// ---------------------------------------------------------------------------
// PTX helpers (sm_80-era only — must be valid under compute_103 virtual arch)
// ---------------------------------------------------------------------------
__device__ __forceinline__ uint32_t smem_u32(const void* p) {
    uint32_t a;
    asm("{ .reg .u64 t; cvta.to.shared.u64 t, %1; cvt.u32.u64 %0, t; }"
        : "=r"(a) : "l"(p));
    return a;
}
__device__ __forceinline__ void cpa16(uint32_t dst, const void* src) {
    asm volatile("cp.async.cg.shared.global [%0], [%1], 16;\n" :: "r"(dst), "l"(src));
}
__device__ __forceinline__ void cpa_commit() {
    asm volatile("cp.async.commit_group;\n" ::: "memory");
}
template <int N>
__device__ __forceinline__ void cpa_wait() {
    asm volatile("cp.async.wait_group %0;\n" :: "n"(N) : "memory");
}
__device__ __forceinline__ void ldsm4(uint32_t* r, uint32_t addr) {
    asm volatile("ldmatrix.sync.aligned.m8n8.x4.shared.b16 {%0,%1,%2,%3}, [%4];"
                 : "=r"(r[0]), "=r"(r[1]), "=r"(r[2]), "=r"(r[3]) : "r"(addr));
}
__device__ __forceinline__ void mma16816(float* d, const uint32_t* a, const uint32_t* b) {
    asm volatile(
        "mma.sync.aligned.m16n8k16.row.col.f32.bf16.bf16.f32 "
        "{%0,%1,%2,%3}, {%4,%5,%6,%7}, {%8,%9}, {%0,%1,%2,%3};"
        : "+f"(d[0]), "+f"(d[1]), "+f"(d[2]), "+f"(d[3])
        : "r"(a[0]), "r"(a[1]), "r"(a[2]), "r"(a[3]), "r"(b[0]), "r"(b[1]));
}
__device__ __forceinline__ uint32_t swz(uint32_t off) {
    return off ^ ((off >> 3) & 0x70);
}

// ---------------------------------------------------------------------------
// mma.sync NT GEMM:  C[M,N] = alpha * (A[M,K] @ B[N,K]^T)
// A = Ahi + Alo, B = Bhi + Blo (bf16 split); fp32 accumulate; 3-term product.
// Tile: 128x128, 8 warps (4 x 2), warp tile 32x64, K chunks of 64 bf16.
// grid = (N/128, M/128, batch). OUTBF=1: write bf16 hi/lo; else fp32.
// ---------------------------------------------------------------------------
#define STG 65536                     // Ahi 16K | Alo 16K | Bhi 16K | Blo 16K
#define SMEM_TOTAL (2 * STG)          // 128 KB, double-buffered

template <int OUTBF>
__global__ void __launch_bounds__(256, 1) gemm_mma(
    const __nv_bfloat16* __restrict__ Ahi, const __nv_bfloat16* __restrict__ Alo,
    const __nv_bfloat16* __restrict__ Bhi, const __nv_bfloat16* __restrict__ Blo,
    float* __restrict__ C, __nv_bfloat16* __restrict__ Chi, __nv_bfloat16* __restrict__ Clo,
    int K, int lda, int ldb, int ldc,
    long long sA, long long sB, long long sC, float alpha)
{
    extern __shared__ __align__(1024) char smem[];
    const uint32_t sbase = smem_u32(smem);
    const int tid = threadIdx.x;
    const int wid = tid >> 5, lane = tid & 31;
    const long long bz = blockIdx.z;
    const int row0 = blockIdx.y * 128;
    const int col0 = blockIdx.x * 128;

    const char* gAhi = (const char*)(Ahi + bz * sA + (long long)row0 * lda);
    const char* gAlo = (const char*)(Alo + bz * sA + (long long)row0 * lda);
    const char* gBhi = (const char*)(Bhi + bz * sB + (long long)col0 * ldb);
    const char* gBlo = (const char*)(Blo + bz * sB + (long long)col0 * ldb);
    const long long ldab = (long long)lda * 2;
    const long long ldbb = (long long)ldb * 2;

    auto load_stage = [&](int c) {
        const uint32_t sb = sbase + ((c & 1) ? (uint32_t)STG : 0u);
        const long long kb = (long long)c * 128;    // 64 bf16 = 128 B per chunk
#pragma unroll
        for (int i = 0; i < 4; i++) {
            const int id = tid + (i << 8);          // 0..1023
            const uint32_t r = id >> 3, cb = (id & 7) << 4;
            const uint32_t off = swz((r << 7) + cb);
            const long long ga = (long long)r * ldab + kb + cb;
            const long long gb = (long long)r * ldbb + kb + cb;
            cpa16(sb + off,          gAhi + ga);
            cpa16(sb + 16384 + off,  gAlo + ga);
            cpa16(sb + 32768 + off,  gBhi + gb);
            cpa16(sb + 49152 + off,  gBlo + gb);
        }
        cpa_commit();
    };

    const int NC = K >> 6;
    const int warp_m = wid & 3;       // 4 warps down M (32 rows each)
    const int warp_n = wid >> 2;      // 2 warps across N (64 cols each)
    const int lrow = lane & 15;
    const uint32_t klane = (lane >> 4) << 4;

    float acc[2][8][4];
#pragma unroll
    for (int i = 0; i < 2; i++)
#pragma unroll
        for (int j = 0; j < 8; j++)
#pragma unroll
            for (int k = 0; k < 4; k++) acc[i][j][k] = 0.0f;

    load_stage(0);

    for (int c = 0; c < NC; c++) {
        if (c + 1 < NC) { load_stage(c + 1); cpa_wait<1>(); }
        else            { cpa_wait<0>(); }
        __syncthreads();

        const uint32_t sb = sbase + ((c & 1) ? (uint32_t)STG : 0u);
#pragma unroll
        for (int ks = 0; ks < 4; ks++) {
            const uint32_t kbyte = (ks << 5) + klane;
            uint32_t ah[2][4], al[2][4];
#pragma unroll
            for (int mt = 0; mt < 2; mt++) {
                const uint32_t off =
                    swz((uint32_t)((warp_m * 32 + mt * 16 + lrow) << 7) + kbyte);
                ldsm4(ah[mt], sb + off);
                ldsm4(al[mt], sb + 16384 + off);
            }
            uint32_t bh[4][4], bl[4][4];
#pragma unroll
            for (int ng = 0; ng < 4; ng++) {
                const uint32_t off =
                    swz((uint32_t)((warp_n * 64 + ng * 16 + lrow) << 7) + kbyte);
                ldsm4(bh[ng], sb + 32768 + off);
                ldsm4(bl[ng], sb + 49152 + off);
            }
#pragma unroll
            for (int mt = 0; mt < 2; mt++)
#pragma unroll
                for (int nt = 0; nt < 8; nt++) {
                    const int ng = nt >> 1, j = nt & 1;
                    uint32_t B0[2] = { bh[ng][j], bh[ng][j + 2] };
                    uint32_t L0[2] = { bl[ng][j], bl[ng][j + 2] };
                    mma16816(acc[mt][nt], ah[mt], B0);   // hi*hi
                    mma16816(acc[mt][nt], al[mt], B0);   // lo*hi
                    mma16816(acc[mt][nt], ah[mt], L0);   // hi*lo
                }
        }
        __syncthreads();
    }

    // Epilogue: c-fragment: {c0,c1}=row lane/4, cols 2(lane%4),+1; {c2,c3}=row+8
    const int rw = row0 + warp_m * 32 + (lane >> 2);
    const int cw = col0 + warp_n * 64 + (lane & 3) * 2;
#pragma unroll
    for (int mt = 0; mt < 2; mt++)
#pragma unroll
        for (int nt = 0; nt < 8; nt++) {
            const int cc = cw + nt * 8;
#pragma unroll
            for (int h = 0; h < 2; h++) {
                const int r = rw + mt * 16 + h * 8;
                const float v0 = alpha * acc[mt][nt][h * 2 + 0];
                const float v1 = alpha * acc[mt][nt][h * 2 + 1];
                const long long ci = bz * sC + (long long)r * ldc + cc;
                if (OUTBF) {
                    const __nv_bfloat16 h0 = __float2bfloat16(v0);
                    const __nv_bfloat16 h1 = __float2bfloat16(v1);
                    ushort2 H, L;
                    H.x = __bfloat16_as_ushort(h0);
                    H.y = __bfloat16_as_ushort(h1);
                    L.x = __bfloat16_as_ushort(__float2bfloat16(v0 - __bfloat162float(h0)));
                    L.y = __bfloat16_as_ushort(__float2bfloat16(v1 - __bfloat162float(h1)));
                    *(ushort2*)&Chi[ci] = H;
                    *(ushort2*)&Clo[ci] = L;
                } else {
                    float2 o; o.x = v0; o.y = v1;
                    *(float2*)&C[ci] = o;
                }
            }
        }
}

// ---------------------------------------------------------------------------
// fp32 -> bf16 hi/lo split (vectorized)
// ---------------------------------------------------------------------------
__global__ void __launch_bounds__(256) split_k(
    const float* __restrict__ in, __nv_bfloat16* __restrict__ hi,
    __nv_bfloat16* __restrict__ lo, long long n4)
{
    long long i = blockIdx.x * (long long)blockDim.x + threadIdx.x;
    const long long stride = (long long)gridDim.x * blockDim.x;
    const float4* in4 = (const float4*)in;
    ushort4* h4 = (ushort4*)hi;
    ushort4* l4 = (ushort4*)lo;
    for (; i < n4; i += stride) {
        const float4 v = in4[i];
        const __nv_bfloat16 a = __float2bfloat16(v.x);
        const __nv_bfloat16 b = __float2bfloat16(v.y);
        const __nv_bfloat16 c = __float2bfloat16(v.z);
        const __nv_bfloat16 d = __float2bfloat16(v.w);
        ushort4 H;
        H.x = __bfloat16_as_ushort(a); H.y = __bfloat16_as_ushort(b);
        H.z = __bfloat16_as_ushort(c); H.w = __bfloat16_as_ushort(d);
        ushort4 L;
        L.x = __bfloat16_as_ushort(__float2bfloat16(v.x - __bfloat162float(a)));
        L.y = __bfloat16_as_ushort(__float2bfloat16(v.y - __bfloat162float(b)));
        L.z = __bfloat16_as_ushort(__float2bfloat16(v.z - __bfloat162float(c)));
        L.w = __bfloat16_as_ushort(__float2bfloat16(v.w - __bfloat162float(d)));
        h4[i] = H;
        l4[i] = L;
    }
}

// ---------------------------------------------------------------------------
// Row softmax over TT=2048 cols; output split to bf16 hi/lo.
// ---------------------------------------------------------------------------
__global__ void __launch_bounds__(256) softmax_split(
    const float* __restrict__ S, __nv_bfloat16* __restrict__ Phi,
    __nv_bfloat16* __restrict__ Plo)
{
    __shared__ float red[8];
    const float* p = S + (long long)blockIdx.x * TT;
    const int tid = threadIdx.x;

    float vals[8];
    float m = -3.4e38f;
#pragma unroll
    for (int i = 0; i < 8; ++i) {
        vals[i] = p[tid + 256 * i];
        m = fmaxf(m, vals[i]);
    }
#pragma unroll
    for (int o = 16; o > 0; o >>= 1) m = fmaxf(m, __shfl_xor_sync(0xffffffffu, m, o));
    if ((tid & 31) == 0) red[tid >> 5] = m;
    __syncthreads();
    float M = red[0];
#pragma unroll
    for (int i = 1; i < 8; ++i) M = fmaxf(M, red[i]);

    float s = 0.0f;
#pragma unroll
    for (int i = 0; i < 8; ++i) { vals[i] = __expf(vals[i] - M); s += vals[i]; }
#pragma unroll
    for (int o = 16; o > 0; o >>= 1) s += __shfl_xor_sync(0xffffffffu, s, o);
    __syncthreads();
    if ((tid & 31) == 0) red[tid >> 5] = s;
    __syncthreads();
    float tot = red[0];
#pragma unroll
    for (int i = 1; i < 8; ++i) tot += red[i];

    const float inv = 1.0f / tot;
    __nv_bfloat16* ph = Phi + (long long)blockIdx.x * TT;
    __nv_bfloat16* pl = Plo + (long long)blockIdx.x * TT;
#pragma unroll
    for (int i = 0; i < 8; ++i) {
        const float v = vals[i] * inv;
        const __nv_bfloat16 h = __float2bfloat16(v);
        ph[tid + 256 * i] = h;
        pl[tid + 256 * i] = __float2bfloat16(v - __bfloat162float(h));
    }
}

// ---------------------------------------------------------------------------
// Launch sequence
// ---------------------------------------------------------------------------
extern "C" void kernel_launch(void* const* d_in, const int* in_sizes, int n_in,
                              void* d_out, int out_size)
{
    (void)in_sizes; (void)n_in; (void)out_size;
    const float* x  = (const float*)d_in[0];
    const float* Wq = (const float*)d_in[1];
    const float* Wk = (const float*)d_in[2];
    const float* Wv = (const float*)d_in[3];
    const float* Wo = (const float*)d_in[4];
    float* out = (float*)d_out;

    __nv_bfloat16 *xhi, *xlo, *wqhi, *wqlo, *wkhi, *wklo, *wvhi, *wvlo, *wohi, *wolo;
    __nv_bfloat16 *qhi, *qlo, *khi, *klo, *vthi, *vtlo, *phi, *plo, *ohi, *olo;
    float* S;
    cudaGetSymbolAddress((void**)&xhi, g_xhi);   cudaGetSymbolAddress((void**)&xlo, g_xlo);
    cudaGetSymbolAddress((void**)&wqhi, g_wqhi); cudaGetSymbolAddress((void**)&wqlo, g_wqlo);
    cudaGetSymbolAddress((void**)&wkhi, g_wkhi); cudaGetSymbolAddress((void**)&wklo, g_wklo);
    cudaGetSymbolAddress((void**)&wvhi, g_wvhi); cudaGetSymbolAddress((void**)&wvlo, g_wvlo);
    cudaGetSymbolAddress((void**)&wohi, g_wohi); cudaGetSymbolAddress((void**)&wolo, g_wolo);
    cudaGetSymbolAddress((void**)&qhi, g_qhi);   cudaGetSymbolAddress((void**)&qlo, g_qlo);
    cudaGetSymbolAddress((void**)&khi, g_khi);   cudaGetSymbolAddress((void**)&klo, g_klo);
    cudaGetSymbolAddress((void**)&vthi, g_vthi); cudaGetSymbolAddress((void**)&vtlo, g_vtlo);
    cudaGetSymbolAddress((void**)&phi, g_phi);   cudaGetSymbolAddress((void**)&plo, g_plo);
    cudaGetSymbolAddress((void**)&ohi, g_ohi);   cudaGetSymbolAddress((void**)&olo, g_olo);
    cudaGetSymbolAddress((void**)&S, g_s);

    cudaFuncSetAttribute(gemm_mma<0>, cudaFuncAttributeMaxDynamicSharedMemorySize, SMEM_TOTAL);
    cudaFuncSetAttribute(gemm_mma<1>, cudaFuncAttributeMaxDynamicSharedMemorySize, SMEM_TOTAL);

    const dim3 blk(256);

    // 0) split inputs
    split_k<<<2048, blk>>>(x,  xhi,  xlo,  (long long)MTOT * NXC / 4);
    split_k<<<256,  blk>>>(Wq, wqhi, wqlo, (long long)NHC * NXC / 4);
    split_k<<<256,  blk>>>(Wk, wkhi, wklo, (long long)NHC * NXC / 4);
    split_k<<<256,  blk>>>(Wv, wvhi, wvlo, (long long)NHC * NXC / 4);
    split_k<<<256,  blk>>>(Wo, wohi, wolo, (long long)NHC * NHC / 4);

    // 1) q = x @ Wq^T, k = x @ Wk^T   [16384 x 1024]
    {
        dim3 g(NHC / 128, MTOT / 128, 1);
        gemm_mma<1><<<g, blk, SMEM_TOTAL>>>(xhi, xlo, wqhi, wqlo,
                                            nullptr, qhi, qlo,
                                            NXC, NXC, NXC, NHC, 0, 0, 0, 1.0f);
        gemm_mma<1><<<g, blk, SMEM_TOTAL>>>(xhi, xlo, wkhi, wklo,
                                            nullptr, khi, klo,
                                            NXC, NXC, NXC, NHC, 0, 0, 0, 1.0f);
    }

    // 2) vT[h, b*T+t] = Wv @ x^T     [1024 x 16384]
    {
        dim3 g(MTOT / 128, NHC / 128, 1);
        gemm_mma<1><<<g, blk, SMEM_TOTAL>>>(wvhi, wvlo, xhi, xlo,
                                            nullptr, vthi, vtlo,
                                            NXC, NXC, NXC, MTOT, 0, 0, 0, 1.0f);
    }

    // 3) scores: S_b = (q_b @ k_b^T) / sqrt(T)   [2048 x 2048] x 8
    {
        dim3 g(TT / 128, TT / 128, BB);
        gemm_mma<0><<<g, blk, SMEM_TOTAL>>>(qhi, qlo, khi, klo,
                                            S, nullptr, nullptr,
                                            NHC, NHC, NHC, TT,
                                            (long long)TT * NHC, (long long)TT * NHC,
                                            (long long)TT * TT, 0.022097086912079608f);
    }

    // 4) softmax rows -> P (bf16 split)
    softmax_split<<<BB * TT, blk>>>(S, phi, plo);

    // 5) o_b = P_b @ vT_b^T          [2048 x 1024] x 8
    {
        dim3 g(NHC / 128, TT / 128, BB);
        gemm_mma<1><<<g, blk, SMEM_TOTAL>>>(phi, plo, vthi, vtlo,
                                            nullptr, ohi, olo,
                                            TT, TT, MTOT, NHC,
                                            (long long)TT * TT, (long long)TT,
                                            (long long)TT * NHC, 1.0f);
    }

    // 6) out = o @ Wo^T              [16384 x 1024]
    {
        dim3 g(NHC / 128, MTOT / 128, 1);
        gemm_mma<0><<<g, blk, SMEM_TOTAL>>>(ohi, olo, wohi, wolo,
                                            out, nullptr, nullptr,
                                            NHC, NHC, NHC, NHC, 0, 0, 0, 1.0f);
    }
}